// round 5
// baseline (speedup 1.0000x reference)
#include <cuda_runtime.h>

#define TILE 128
#define DIMS 64
#define KNN 16
#define NPTS 8192
#define SA_STRIDE 68     // As/Bs row stride (floats): conflict-free mainloop LDS
#define DS_STRIDE 136    // Ds row stride: epilogue STS bank = 8*wy+wx (conflict-free)

// packed fp32x2 FMA (sm_103a): d = a*b + c elementwise on 2-float lanes
#define FMA2(acc, a, b) \
    asm("fma.rn.f32x2 %0, %1, %2, %0;" : "+l"(acc) : "l"(a), "l"(b))

__global__ __launch_bounds__(256, 1)
void knn_tiled(const float* __restrict__ x, float* __restrict__ out) {
    extern __shared__ float smem[];
    float* As  = smem;                          // 128*68
    float* Bs  = As + TILE * SA_STRIDE;         // 128*68
    float* Ds  = Bs + TILE * SA_STRIDE;         // 128*136
    float* sqA = Ds + TILE * DS_STRIDE;         // 128
    float* sqB = sqA + TILE;                    // 128
    float* kds = sqB + TILE;                    // 128*16
    int*   kis = (int*)(kds + TILE * KNN);      // 128*16

    const int tid    = threadIdx.x;
    const int lane   = tid & 31;
    const int warp   = tid >> 5;
    const int wx     = lane & 7;
    const int wy     = lane >> 3;
    const int warp_x = warp & 1;
    const int warp_y = warp >> 1;
    const int batch  = blockIdx.y;
    const int row0   = blockIdx.x * TILE;
    const float* xb  = x + (size_t)batch * NPTS * DIMS;

    const float INF = __int_as_float(0x7f800000);

    // per-thread top-k state: thread t (t<128) owns query row row0+t
    float kth = INF;
    if (tid < TILE) {
        #pragma unroll
        for (int j = 0; j < KNN; j++) { kds[tid * KNN + j] = INF; kis[tid * KNN + j] = 0; }
    }

    // load A tile, coalesced
    for (int i = tid; i < TILE * (DIMS / 4); i += 256) {
        int r = i >> 4, d4 = i & 15;
        *(float4*)&As[r * SA_STRIDE + 4 * d4] =
            *(const float4*)&xb[(size_t)(row0 + r) * DIMS + 4 * d4];
    }
    __syncthreads();
    if (tid < TILE) {
        float s0 = 0.f, s1 = 0.f, s2 = 0.f, s3 = 0.f;
        #pragma unroll
        for (int d4 = 0; d4 < 16; d4++) {
            float4 v = *(float4*)&As[tid * SA_STRIDE + 4 * d4];
            s0 = fmaf(v.x, v.x, s0); s1 = fmaf(v.y, v.y, s1);
            s2 = fmaf(v.z, v.z, s2); s3 = fmaf(v.w, v.w, s3);
        }
        sqA[tid] = (s0 + s1) + (s2 + s3);
    }

    const int rbase = warp_y * 32 + wy;   // thread rows: rbase + 4*m
    const int cbase = warp_x * 64 + wx;   // thread cols: cbase + 8*n

    for (int t = 0; t < NPTS / TILE; t++) {
        const int col0 = t * TILE;

        // load B tile
        for (int i = tid; i < TILE * (DIMS / 4); i += 256) {
            int r = i >> 4, d4 = i & 15;
            *(float4*)&Bs[r * SA_STRIDE + 4 * d4] =
                *(const float4*)&xb[(size_t)(col0 + r) * DIMS + 4 * d4];
        }
        __syncthreads();   // Bs visible
        if (tid < TILE) {
            float s0 = 0.f, s1 = 0.f, s2 = 0.f, s3 = 0.f;
            #pragma unroll
            for (int d4 = 0; d4 < 16; d4++) {
                float4 v = *(float4*)&Bs[tid * SA_STRIDE + 4 * d4];
                s0 = fmaf(v.x, v.x, s0); s1 = fmaf(v.y, v.y, s1);
                s2 = fmaf(v.z, v.z, s2); s3 = fmaf(v.w, v.w, s3);
            }
            sqB[tid] = (s0 + s1) + (s2 + s3);
        }
        __syncthreads();   // sqB visible

        // ---- 128x128x64 GEMM, K packed into f32x2 lanes (even/odd dims) ----
        unsigned long long acc2[8][8];
        #pragma unroll
        for (int m = 0; m < 8; m++)
            #pragma unroll
            for (int n = 0; n < 8; n++) acc2[m][n] = 0ull;   // {0f,0f}

        #pragma unroll 4
        for (int d4 = 0; d4 < 16; d4++) {
            unsigned long long a0[8], a1[8], b0[8], b1[8];
            #pragma unroll
            for (int m = 0; m < 8; m++) {
                ulonglong2 v = *(ulonglong2*)&As[(rbase + 4 * m) * SA_STRIDE + 4 * d4];
                a0[m] = v.x; a1[m] = v.y;
            }
            #pragma unroll
            for (int n = 0; n < 8; n++) {
                ulonglong2 v = *(ulonglong2*)&Bs[(cbase + 8 * n) * SA_STRIDE + 4 * d4];
                b0[n] = v.x; b1[n] = v.y;
            }
            #pragma unroll
            for (int m = 0; m < 8; m++)
                #pragma unroll
                for (int n = 0; n < 8; n++) {
                    FMA2(acc2[m][n], a0[m], b0[n]);
                    FMA2(acc2[m][n], a1[m], b1[n]);
                }
        }

        // epilogue: dist into Ds (scalar STS, conflict-free by stride 136)
        #pragma unroll
        for (int m = 0; m < 8; m++) {
            const int r = rbase + 4 * m;
            const float sa = sqA[r];
            #pragma unroll
            for (int n = 0; n < 8; n++) {
                const int c = cbase + 8 * n;
                float lo = __uint_as_float((unsigned)(acc2[m][n] & 0xffffffffull));
                float hi = __uint_as_float((unsigned)(acc2[m][n] >> 32));
                const float acc = lo + hi;
                Ds[r * DS_STRIDE + c] = (sa - 2.f * acc) + sqB[c];
            }
        }
        __syncthreads();   // Ds visible

        // ---- selection: thread t owns row t; stable ascending scan ----
        if (tid < TILE) {
            const int base = tid * KNN;
            #pragma unroll 4
            for (int c4 = 0; c4 < TILE / 4; c4++) {
                float4 dv = *(float4*)&Ds[tid * DS_STRIDE + 4 * c4];
                #pragma unroll
                for (int e = 0; e < 4; e++) {
                    const float d = (e == 0) ? dv.x : (e == 1) ? dv.y
                                  : (e == 2) ? dv.z : dv.w;
                    if (d < kth) {                      // rare
                        int j = KNN - 1;
                        while (j > 0 && kds[base + j - 1] > d) {
                            kds[base + j] = kds[base + j - 1];
                            kis[base + j] = kis[base + j - 1];
                            j--;
                        }
                        kds[base + j] = d;
                        kis[base + j] = col0 + 4 * c4 + e;
                        kth = kds[base + KNN - 1];
                    }
                }
            }
        }
        __syncthreads();   // lists settled before Bs/Ds overwritten
    }

    // ---- output (float): out[0]=nn_idx (B,N,K), out[1]=center_idx ----
    if (tid < TILE) {
        float* out_nn = out;
        float* out_c  = out + 2 * NPTS * KNN;
        const int grow = row0 + tid;
        const size_t obase = ((size_t)batch * NPTS + grow) * KNN;
        #pragma unroll
        for (int j = 0; j < KNN; j++) {
            out_nn[obase + j] = (float)kis[tid * KNN + j];
            out_c [obase + j] = (float)grow;
        }
    }
}

extern "C" void kernel_launch(void* const* d_in, const int* in_sizes, int n_in,
                              void* d_out, int out_size) {
    const float* x = (const float*)d_in[0];
    float* out = (float*)d_out;

    const size_t smem_bytes =
        (size_t)(TILE * SA_STRIDE * 2 + TILE * DS_STRIDE + 2 * TILE + TILE * KNN) * 4
        + (size_t)TILE * KNN * 4;

    cudaFuncSetAttribute(knn_tiled,
                         cudaFuncAttributeMaxDynamicSharedMemorySize,
                         (int)smem_bytes);

    dim3 grid(NPTS / TILE, 2);
    knn_tiled<<<grid, 256, smem_bytes>>>(x, out);
}

// round 6
// speedup vs baseline: 1.4946x; 1.4946x over previous
#include <cuda_runtime.h>

#define KNN 16
#define NPTS 8192
#define DIMS 64
#define TILE 128
#define AST 65    // ull stride per-d for As_T  (64 row-pairs + 1 pad)
#define BST 131   // ull stride per-d for BsDup (128 cols + 3 pad)
#define DST 132   // float stride for Ds: epilogue bank = 8*wy+wx+const (free)

// packed fp32x2 FMA (sm_103a): acc = a*b + acc elementwise on 2 fp32 lanes
#define FMA2(acc, a, b) \
    asm("fma.rn.f32x2 %0, %1, %2, %0;" : "+l"(acc) : "l"(a), "l"(b))

__global__ __launch_bounds__(256, 1)
void knn_tiled2(const float* __restrict__ x, float* __restrict__ out) {
    extern __shared__ unsigned long long smem_u64[];
    unsigned long long* AsT = smem_u64;                 // [64][AST] ull
    unsigned long long* BsD = AsT + DIMS * AST;         // [64][BST] ull
    float* Ds  = (float*)(BsD + DIMS * BST);            // [128][DST]
    float* sqA = Ds + TILE * DST;                       // 128
    float* sqB = sqA + TILE;                            // 128
    float* kds = sqB + TILE;                            // 128*16
    int*   kis = (int*)(kds + TILE * KNN);              // 128*16
    float* AsTf = (float*)AsT;                          // As_T as floats: [d][row], row stride 2*AST

    const int tid    = threadIdx.x;
    const int lane   = tid & 31;
    const int warp   = tid >> 5;
    const int wy     = lane >> 3;      // 0..3
    const int wx     = lane & 7;       // 0..7
    const int warp_y = warp >> 1;      // 0..3
    const int warp_x = warp & 1;       // 0..1
    const int batch  = blockIdx.y;
    const int row0   = blockIdx.x * TILE;
    const float* xb  = x + (size_t)batch * NPTS * DIMS;

    const float INF = __int_as_float(0x7f800000);

    float kth = INF;
    if (tid < TILE) {
        #pragma unroll
        for (int j = 0; j < KNN; j++) { kds[tid * KNN + j] = INF; kis[tid * KNN + j] = 0; }
    }

    // ---- A tile: transpose store As_T[d][row] (lanes take consecutive rows,
    //      smem stores conflict-free; gmem scattered but L2-resident) ----
    for (int i = tid; i < TILE * (DIMS / 4); i += 256) {
        const int d4 = i >> 7;         // 0..15
        const int r  = i & 127;        // 0..127, consecutive per lane
        float4 v = *(const float4*)&xb[(size_t)(row0 + r) * DIMS + 4 * d4];
        AsTf[(4 * d4 + 0) * (2 * AST) + r] = v.x;
        AsTf[(4 * d4 + 1) * (2 * AST) + r] = v.y;
        AsTf[(4 * d4 + 2) * (2 * AST) + r] = v.z;
        AsTf[(4 * d4 + 3) * (2 * AST) + r] = v.w;
    }
    // sqA: single sequential fma chain over d (matches mainloop lane chains)
    if (tid < TILE) {
        float s = 0.f;
        const float* p = &xb[(size_t)(row0 + tid) * DIMS];
        #pragma unroll
        for (int d4 = 0; d4 < 16; d4++) {
            float4 v = *(const float4*)&p[4 * d4];
            s = fmaf(v.x, v.x, s); s = fmaf(v.y, v.y, s);
            s = fmaf(v.z, v.z, s); s = fmaf(v.w, v.w, s);
        }
        sqA[tid] = s;
    }

    const int prbase = 16 * warp_y + wy;            // pairs: prbase + 4*p
    const int cbase  = 64 * warp_x + wx;            // cols:  cbase + 8*n

    for (int t = 0; t < NPTS / TILE; t++) {
        const int col0 = t * TILE;

        __syncthreads();   // prev tile consumed (selection done); also A ready (t=0)

        // ---- B tile: duplicated transpose BsDup[d][c] = {v,v} ----
        for (int i = tid; i < TILE * (DIMS / 4); i += 256) {
            const int d4 = i >> 7;
            const int r  = i & 127;
            float4 v = *(const float4*)&xb[(size_t)(col0 + r) * DIMS + 4 * d4];
            unsigned long long dx, dy, dz, dw;
            asm("mov.b64 %0, {%1, %1};" : "=l"(dx) : "f"(v.x));
            asm("mov.b64 %0, {%1, %1};" : "=l"(dy) : "f"(v.y));
            asm("mov.b64 %0, {%1, %1};" : "=l"(dz) : "f"(v.z));
            asm("mov.b64 %0, {%1, %1};" : "=l"(dw) : "f"(v.w));
            BsD[(4 * d4 + 0) * BST + r] = dx;
            BsD[(4 * d4 + 1) * BST + r] = dy;
            BsD[(4 * d4 + 2) * BST + r] = dz;
            BsD[(4 * d4 + 3) * BST + r] = dw;
        }
        if (tid < TILE) {
            float s = 0.f;
            const float* p = &xb[(size_t)(col0 + tid) * DIMS];
            #pragma unroll
            for (int d4 = 0; d4 < 16; d4++) {
                float4 v = *(const float4*)&p[4 * d4];
                s = fmaf(v.x, v.x, s); s = fmaf(v.y, v.y, s);
                s = fmaf(v.z, v.z, s); s = fmaf(v.w, v.w, s);
            }
            sqB[tid] = s;
        }
        __syncthreads();   // BsD + sqB visible

        // ---- mainloop: 128x128x64, M-packed f32x2 (acc lanes = 2 rows) ----
        unsigned long long acc2[4][8];
        #pragma unroll
        for (int p = 0; p < 4; p++)
            #pragma unroll
            for (int n = 0; n < 8; n++) acc2[p][n] = 0ull;

        const unsigned long long* aptr = AsT + prbase;
        const unsigned long long* bptr = BsD + cbase;

        #pragma unroll 4
        for (int d = 0; d < DIMS; d++) {
            unsigned long long a2[4], bd[8];
            #pragma unroll
            for (int p = 0; p < 4; p++) a2[p] = aptr[d * AST + 4 * p];
            #pragma unroll
            for (int n = 0; n < 8; n++) bd[n] = bptr[d * BST + 8 * n];
            #pragma unroll
            for (int p = 0; p < 4; p++)
                #pragma unroll
                for (int n = 0; n < 8; n++) FMA2(acc2[p][n], a2[p], bd[n]);
        }

        // ---- epilogue: dist into Ds (conflict-free by DST=132) ----
        #pragma unroll
        for (int p = 0; p < 4; p++) {
            const int r0 = 2 * (prbase + 4 * p);
            const float sa0 = sqA[r0], sa1 = sqA[r0 + 1];
            #pragma unroll
            for (int n = 0; n < 8; n++) {
                const int c = cbase + 8 * n;
                float lo, hi;
                asm("mov.b64 {%0, %1}, %2;" : "=f"(lo), "=f"(hi) : "l"(acc2[p][n]));
                const float sb = sqB[c];
                Ds[r0 * DST + c]       = (sa0 - 2.f * lo) + sb;
                Ds[(r0 + 1) * DST + c] = (sa1 - 2.f * hi) + sb;
            }
        }
        __syncthreads();   // Ds visible

        // ---- selection: thread t owns row t; stable ascending scan ----
        if (tid < TILE) {
            const int base = tid * KNN;
            #pragma unroll 4
            for (int c4 = 0; c4 < TILE / 4; c4++) {
                float4 dv = *(float4*)&Ds[tid * DST + 4 * c4];
                #pragma unroll
                for (int e = 0; e < 4; e++) {
                    const float d = (e == 0) ? dv.x : (e == 1) ? dv.y
                                  : (e == 2) ? dv.z : dv.w;
                    if (d < kth) {                      // rare
                        int j = KNN - 1;
                        while (j > 0 && kds[base + j - 1] > d) {
                            kds[base + j] = kds[base + j - 1];
                            kis[base + j] = kis[base + j - 1];
                            j--;
                        }
                        kds[base + j] = d;
                        kis[base + j] = col0 + 4 * c4 + e;
                        kth = kds[base + KNN - 1];
                    }
                }
            }
        }
        // loop-top __syncthreads separates selection from next B-store
    }

    // ---- output (float): out[0]=nn_idx (B,N,K), out[1]=center_idx ----
    if (tid < TILE) {
        float* out_nn = out;
        float* out_c  = out + 2 * NPTS * KNN;
        const int grow = row0 + tid;
        const size_t obase = ((size_t)batch * NPTS + grow) * KNN;
        #pragma unroll
        for (int j = 0; j < KNN; j++) {
            out_nn[obase + j] = (float)kis[tid * KNN + j];
            out_c [obase + j] = (float)grow;
        }
    }
}

extern "C" void kernel_launch(void* const* d_in, const int* in_sizes, int n_in,
                              void* d_out, int out_size) {
    const float* x = (const float*)d_in[0];
    float* out = (float*)d_out;

    const size_t smem_bytes =
        (size_t)(DIMS * AST + DIMS * BST) * 8 +
        (size_t)(TILE * DST + 2 * TILE + TILE * KNN) * 4 +
        (size_t)TILE * KNN * 4;

    cudaFuncSetAttribute(knn_tiled2,
                         cudaFuncAttributeMaxDynamicSharedMemorySize,
                         (int)smem_bytes);

    dim3 grid(NPTS / TILE, 2);
    knn_tiled2<<<grid, 256, smem_bytes>>>(x, out);
}